// round 1
// baseline (speedup 1.0000x reference)
#include <cuda_runtime.h>
#include <cuda_bf16.h>
#include <cstdint>

// KAT_Group rational activation: out = P5(z; a) / Q4(z; |b|), grouped along last dim.
//   x:  (B, L, D) fp32, D = 2048, G = 8 groups of 256
//   weight_numerator:   (1, 6)  -- shared across groups
//   weight_denominator: (G, 4)  -- b1..b4; denominator poly = |1| + |b1| z + |b2| z^2 + |b3| z^3 + |b4| z^4
//
// Pure HBM-streaming kernel: float4 in/out, group index via mask/shift (no div).

#ifndef KAT_D
#define KAT_D 2048  // last-dim size (fixed for this problem instance)
#endif

__global__ void __launch_bounds__(256)
kat_group_kernel(const float4* __restrict__ x4,
                 const float*  __restrict__ wn,    // 6 numerator coefs (uniform)
                 const float4* __restrict__ wd4,   // G x (b1..b4)
                 float4* __restrict__ out4,
                 int n4, int d4_mask, int dpg4_shift)
{
    int i = blockIdx.x * blockDim.x + threadIdx.x;
    if (i >= n4) return;

    // numerator coefs: uniform across all threads -> L1 broadcast hits
    const float a0 = __ldg(&wn[0]);
    const float a1 = __ldg(&wn[1]);
    const float a2 = __ldg(&wn[2]);
    const float a3 = __ldg(&wn[3]);
    const float a4 = __ldg(&wn[4]);
    const float a5 = __ldg(&wn[5]);

    // group for this float4 (256 elems per group -> 64 float4s per group, aligned)
    const int g = (i & d4_mask) >> dpg4_shift;
    const float4 b = __ldg(&wd4[g]);
    const float b1 = fabsf(b.x);
    const float b2 = fabsf(b.y);
    const float b3 = fabsf(b.z);
    const float b4 = fabsf(b.w);

    const float4 zv = __ldg(&x4[i]);
    float zs[4] = {zv.x, zv.y, zv.z, zv.w};
    float rs[4];

#pragma unroll
    for (int k = 0; k < 4; ++k) {
        const float z = zs[k];
        float num = fmaf(a5, z, a4);
        num = fmaf(num, z, a3);
        num = fmaf(num, z, a2);
        num = fmaf(num, z, a1);
        num = fmaf(num, z, a0);
        float den = fmaf(b4, z, b3);
        den = fmaf(den, z, b2);
        den = fmaf(den, z, b1);
        den = fmaf(den, z, 1.0f);
        rs[k] = __fdividef(num, den);
    }

    out4[i] = make_float4(rs[0], rs[1], rs[2], rs[3]);
}

extern "C" void kernel_launch(void* const* d_in, const int* in_sizes, int n_in,
                              void* d_out, int out_size)
{
    // metadata order: x (f32), weight_numerator (f32, 6), weight_denominator (f32, G*4), num_groups (i32)
    const float4* x4  = (const float4*)d_in[0];
    const float*  wn  = (const float*) d_in[1];
    const float4* wd4 = (const float4*)d_in[2];
    float4* out4 = (float4*)d_out;

    const int n4 = out_size / 4;

    // Group geometry (host-side, from sizes): G = wd_elems / 4, D fixed at KAT_D.
    int G = in_sizes[2] / 4;
    if (G <= 0) G = 8;
    const int d4   = KAT_D / 4;          // float4s per row = 512
    const int dpg4 = d4 / G;             // float4s per group = 64
    int shift = 0;
    while ((1 << shift) < dpg4) ++shift; // log2(dpg4)

    const int threads = 256;
    const int blocks = (n4 + threads - 1) / threads;
    kat_group_kernel<<<blocks, threads>>>(x4, wn, wd4, out4,
                                          n4, d4 - 1, shift);
}

// round 2
// speedup vs baseline: 1.0366x; 1.0366x over previous
#include <cuda_runtime.h>
#include <cuda_bf16.h>
#include <cstdint>

// KAT_Group rational activation: out = P5(z; a) / Q4(z; |b|), grouped along last dim.
//   x:  (B, L, D) fp32, D = 2048, G = 8 groups of 256
//   weight_numerator:   (1, 6)  -- shared across groups
//   weight_denominator: (G, 4)  -- b1..b4; den = 1 + |b1| z + |b2| z^2 + |b3| z^3 + |b4| z^4
//
// HBM-streaming kernel, MLP=4: each thread issues 4 independent float4 loads
// up front (coalesced, stride blockDim), computes, then 4 stores. Streaming
// cache hints since every element is touched exactly once.

#ifndef KAT_D
#define KAT_D 2048
#endif

#define VPT 4  // float4s per thread

__global__ void __launch_bounds__(256)
kat_group_kernel(const float4* __restrict__ x4,
                 const float*  __restrict__ wn,    // 6 numerator coefs (uniform)
                 const float4* __restrict__ wd4,   // G x (b1..b4)
                 float4* __restrict__ out4,
                 int n4, int d4_mask, int dpg4_shift)
{
    const int base = blockIdx.x * (blockDim.x * VPT) + threadIdx.x;

    // ---- front-batched loads: 4 independent LDG.128 in flight (MLP=4) ----
    float4 zv[VPT];
    int    idx[VPT];
    bool   ok[VPT];
#pragma unroll
    for (int k = 0; k < VPT; ++k) {
        idx[k] = base + k * 256;
        ok[k]  = idx[k] < n4;
        if (ok[k]) zv[k] = __ldcs(&x4[idx[k]]);
    }

    // numerator coefs: uniform across all threads -> L1 broadcast
    const float a0 = __ldg(&wn[0]);
    const float a1 = __ldg(&wn[1]);
    const float a2 = __ldg(&wn[2]);
    const float a3 = __ldg(&wn[3]);
    const float a4 = __ldg(&wn[4]);
    const float a5 = __ldg(&wn[5]);

#pragma unroll
    for (int k = 0; k < VPT; ++k) {
        if (!ok[k]) continue;

        // group for this float4 (64 float4s per group, power-of-two geometry)
        const int g = (idx[k] & d4_mask) >> dpg4_shift;
        const float4 b = __ldg(&wd4[g]);
        const float b1 = fabsf(b.x);
        const float b2 = fabsf(b.y);
        const float b3 = fabsf(b.z);
        const float b4 = fabsf(b.w);

        float zs[4] = {zv[k].x, zv[k].y, zv[k].z, zv[k].w};
        float rs[4];
#pragma unroll
        for (int e = 0; e < 4; ++e) {
            const float z = zs[e];
            float num = fmaf(a5, z, a4);
            num = fmaf(num, z, a3);
            num = fmaf(num, z, a2);
            num = fmaf(num, z, a1);
            num = fmaf(num, z, a0);
            float den = fmaf(b4, z, b3);
            den = fmaf(den, z, b2);
            den = fmaf(den, z, b1);
            den = fmaf(den, z, 1.0f);
            rs[e] = __fdividef(num, den);
        }
        __stcs(&out4[idx[k]], make_float4(rs[0], rs[1], rs[2], rs[3]));
    }
}

extern "C" void kernel_launch(void* const* d_in, const int* in_sizes, int n_in,
                              void* d_out, int out_size)
{
    const float4* x4  = (const float4*)d_in[0];
    const float*  wn  = (const float*) d_in[1];
    const float4* wd4 = (const float4*)d_in[2];
    float4* out4 = (float4*)d_out;

    const int n4 = out_size / 4;

    int G = in_sizes[2] / 4;
    if (G <= 0) G = 8;
    const int d4   = KAT_D / 4;          // 512 float4s per row
    const int dpg4 = d4 / G;             // 64 float4s per group
    int shift = 0;
    while ((1 << shift) < dpg4) ++shift;

    const int threads = 256;
    const int per_block = threads * VPT; // 1024 float4s per block
    const int blocks = (n4 + per_block - 1) / per_block;
    kat_group_kernel<<<blocks, threads>>>(x4, wn, wd4, out4,
                                          n4, d4 - 1, shift);
}

// round 4
// speedup vs baseline: 1.0425x; 1.0057x over previous
#include <cuda_runtime.h>
#include <cuda_bf16.h>
#include <cstdint>

// KAT_Group rational activation: out = P5(z; a) / Q4(z; |b|), grouped along last dim.
//   x: (B, L, D) fp32, D = 2048, G = 8 groups of 256.
// Pure HBM streaming; 256-bit vector ld/st (v8.f32) on sm_100+, float4x2 fallback.

#ifndef KAT_D
#define KAT_D 2048
#endif

#define F8PT 2   // float8s per thread
#define TPB  256

struct __align__(32) f8 { float v[8]; };

__device__ __forceinline__ f8 ldg256_cs(const f8* p) {
    f8 r;
#if defined(__CUDA_ARCH__) && (__CUDA_ARCH__ >= 1000)
    asm volatile("ld.global.cs.v8.f32 {%0,%1,%2,%3,%4,%5,%6,%7}, [%8];"
                 : "=f"(r.v[0]), "=f"(r.v[1]), "=f"(r.v[2]), "=f"(r.v[3]),
                   "=f"(r.v[4]), "=f"(r.v[5]), "=f"(r.v[6]), "=f"(r.v[7])
                 : "l"(p));
#else
    const float4* p4 = reinterpret_cast<const float4*>(p);
    float4 lo = __ldcs(p4);
    float4 hi = __ldcs(p4 + 1);
    r.v[0] = lo.x; r.v[1] = lo.y; r.v[2] = lo.z; r.v[3] = lo.w;
    r.v[4] = hi.x; r.v[5] = hi.y; r.v[6] = hi.z; r.v[7] = hi.w;
#endif
    return r;
}

__device__ __forceinline__ void stg256_cs(f8* p, const f8& r) {
#if defined(__CUDA_ARCH__) && (__CUDA_ARCH__ >= 1000)
    asm volatile("st.global.cs.v8.f32 [%0], {%1,%2,%3,%4,%5,%6,%7,%8};"
                 :: "l"(p),
                    "f"(r.v[0]), "f"(r.v[1]), "f"(r.v[2]), "f"(r.v[3]),
                    "f"(r.v[4]), "f"(r.v[5]), "f"(r.v[6]), "f"(r.v[7])
                 : "memory");
#else
    float4* p4 = reinterpret_cast<float4*>(p);
    __stcs(p4,     make_float4(r.v[0], r.v[1], r.v[2], r.v[3]));
    __stcs(p4 + 1, make_float4(r.v[4], r.v[5], r.v[6], r.v[7]));
#endif
}

__global__ void __launch_bounds__(TPB)
kat_group_kernel(const f8* __restrict__ x8,
                 const float*  __restrict__ wn,    // 6 numerator coefs (uniform)
                 const float4* __restrict__ wd4,   // G x (b1..b4)
                 f8* __restrict__ out8,
                 int n8, int d8_mask, int dpg8_shift)
{
    const int base = blockIdx.x * (TPB * F8PT) + threadIdx.x;

    // front-batched 256-bit loads (independent, coalesced)
    f8  zv[F8PT];
    int idx[F8PT];
    bool ok[F8PT];
#pragma unroll
    for (int k = 0; k < F8PT; ++k) {
        idx[k] = base + k * TPB;
        ok[k]  = idx[k] < n8;
        if (ok[k]) zv[k] = ldg256_cs(&x8[idx[k]]);
    }

    // numerator coefs: uniform -> L1 broadcast
    const float a0 = __ldg(&wn[0]);
    const float a1 = __ldg(&wn[1]);
    const float a2 = __ldg(&wn[2]);
    const float a3 = __ldg(&wn[3]);
    const float a4 = __ldg(&wn[4]);
    const float a5 = __ldg(&wn[5]);

#pragma unroll
    for (int k = 0; k < F8PT; ++k) {
        if (!ok[k]) continue;

        const int g = (idx[k] & d8_mask) >> dpg8_shift;  // group uniform over the float8
        const float4 b = __ldg(&wd4[g]);
        const float b1 = fabsf(b.x);
        const float b2 = fabsf(b.y);
        const float b3 = fabsf(b.z);
        const float b4 = fabsf(b.w);

        f8 r;
#pragma unroll
        for (int e = 0; e < 8; ++e) {
            const float z = zv[k].v[e];
            float num = fmaf(a5, z, a4);
            num = fmaf(num, z, a3);
            num = fmaf(num, z, a2);
            num = fmaf(num, z, a1);
            num = fmaf(num, z, a0);
            float den = fmaf(b4, z, b3);
            den = fmaf(den, z, b2);
            den = fmaf(den, z, b1);
            den = fmaf(den, z, 1.0f);
            r.v[e] = __fdividef(num, den);
        }
        stg256_cs(&out8[idx[k]], r);
    }
}

extern "C" void kernel_launch(void* const* d_in, const int* in_sizes, int n_in,
                              void* d_out, int out_size)
{
    const f8*     x8  = (const f8*)    d_in[0];
    const float*  wn  = (const float*) d_in[1];
    const float4* wd4 = (const float4*)d_in[2];
    f8* out8 = (f8*)d_out;

    const int n8 = out_size / 8;

    int G = in_sizes[2] / 4;
    if (G <= 0) G = 8;
    const int d8   = KAT_D / 8;          // 256 float8s per row
    const int dpg8 = d8 / G;             // 32 float8s per group
    int shift = 0;
    while ((1 << shift) < dpg8) ++shift;

    const int per_block = TPB * F8PT;    // 512 float8s per block
    const int blocks = (n8 + per_block - 1) / per_block;
    kat_group_kernel<<<blocks, TPB>>>(x8, wn, wd4, out8,
                                      n8, d8 - 1, shift);
}

// round 5
// speedup vs baseline: 1.0462x; 1.0036x over previous
#include <cuda_runtime.h>
#include <cuda_bf16.h>
#include <cstdint>

// KAT_Group rational activation: out = P5(z; a) / Q4(z; |b|), grouped along last dim.
//   x: (B, L, D) fp32, D = 2048, G = 8 groups of 256.
// Pure HBM streaming; 256-bit vector ld/st (v8.f32), 4 float8s per thread
// front-batched (128B MLP per thread), streaming cache hints.

#ifndef KAT_D
#define KAT_D 2048
#endif

#define F8PT 4   // float8s per thread
#define TPB  256

struct __align__(32) f8 { float v[8]; };

__device__ __forceinline__ f8 ldg256_cs(const f8* p) {
    f8 r;
#if defined(__CUDA_ARCH__) && (__CUDA_ARCH__ >= 1000)
    asm volatile("ld.global.cs.v8.f32 {%0,%1,%2,%3,%4,%5,%6,%7}, [%8];"
                 : "=f"(r.v[0]), "=f"(r.v[1]), "=f"(r.v[2]), "=f"(r.v[3]),
                   "=f"(r.v[4]), "=f"(r.v[5]), "=f"(r.v[6]), "=f"(r.v[7])
                 : "l"(p));
#else
    const float4* p4 = reinterpret_cast<const float4*>(p);
    float4 lo = __ldcs(p4);
    float4 hi = __ldcs(p4 + 1);
    r.v[0] = lo.x; r.v[1] = lo.y; r.v[2] = lo.z; r.v[3] = lo.w;
    r.v[4] = hi.x; r.v[5] = hi.y; r.v[6] = hi.z; r.v[7] = hi.w;
#endif
    return r;
}

__device__ __forceinline__ void stg256_cs(f8* p, const f8& r) {
#if defined(__CUDA_ARCH__) && (__CUDA_ARCH__ >= 1000)
    asm volatile("st.global.cs.v8.f32 [%0], {%1,%2,%3,%4,%5,%6,%7,%8};"
                 :: "l"(p),
                    "f"(r.v[0]), "f"(r.v[1]), "f"(r.v[2]), "f"(r.v[3]),
                    "f"(r.v[4]), "f"(r.v[5]), "f"(r.v[6]), "f"(r.v[7])
                 : "memory");
#else
    float4* p4 = reinterpret_cast<float4*>(p);
    __stcs(p4,     make_float4(r.v[0], r.v[1], r.v[2], r.v[3]));
    __stcs(p4 + 1, make_float4(r.v[4], r.v[5], r.v[6], r.v[7]));
#endif
}

__global__ void __launch_bounds__(TPB)
kat_group_kernel(const f8* __restrict__ x8,
                 const float*  __restrict__ wn,    // 6 numerator coefs (uniform)
                 const float4* __restrict__ wd4,   // G x (b1..b4)
                 f8* __restrict__ out8,
                 int n8, int d8_mask, int dpg8_shift)
{
    const int base = blockIdx.x * (TPB * F8PT) + threadIdx.x;

    // front-batched 256-bit loads: 4 independent LDG in flight per thread
    f8  zv[F8PT];
    int idx[F8PT];
    bool ok[F8PT];
#pragma unroll
    for (int k = 0; k < F8PT; ++k) {
        idx[k] = base + k * TPB;
        ok[k]  = idx[k] < n8;
        if (ok[k]) zv[k] = ldg256_cs(&x8[idx[k]]);
    }

    // numerator coefs: uniform -> L1 broadcast
    const float a0 = __ldg(&wn[0]);
    const float a1 = __ldg(&wn[1]);
    const float a2 = __ldg(&wn[2]);
    const float a3 = __ldg(&wn[3]);
    const float a4 = __ldg(&wn[4]);
    const float a5 = __ldg(&wn[5]);

#pragma unroll
    for (int k = 0; k < F8PT; ++k) {
        if (!ok[k]) continue;

        const int g = (idx[k] & d8_mask) >> dpg8_shift;  // group uniform over the float8
        const float4 b = __ldg(&wd4[g]);
        const float b1 = fabsf(b.x);
        const float b2 = fabsf(b.y);
        const float b3 = fabsf(b.z);
        const float b4 = fabsf(b.w);

        f8 r;
#pragma unroll
        for (int e = 0; e < 8; ++e) {
            const float z = zv[k].v[e];
            float num = fmaf(a5, z, a4);
            num = fmaf(num, z, a3);
            num = fmaf(num, z, a2);
            num = fmaf(num, z, a1);
            num = fmaf(num, z, a0);
            float den = fmaf(b4, z, b3);
            den = fmaf(den, z, b2);
            den = fmaf(den, z, b1);
            den = fmaf(den, z, 1.0f);
            r.v[e] = __fdividef(num, den);
        }
        stg256_cs(&out8[idx[k]], r);
    }
}

extern "C" void kernel_launch(void* const* d_in, const int* in_sizes, int n_in,
                              void* d_out, int out_size)
{
    const f8*     x8  = (const f8*)    d_in[0];
    const float*  wn  = (const float*) d_in[1];
    const float4* wd4 = (const float4*)d_in[2];
    f8* out8 = (f8*)d_out;

    const int n8 = out_size / 8;

    int G = in_sizes[2] / 4;
    if (G <= 0) G = 8;
    const int d8   = KAT_D / 8;          // 256 float8s per row
    const int dpg8 = d8 / G;             // 32 float8s per group
    int shift = 0;
    while ((1 << shift) < dpg8) ++shift;

    const int per_block = TPB * F8PT;    // 1024 float8s per block
    const int blocks = (n8 + per_block - 1) / per_block;
    kat_group_kernel<<<blocks, TPB>>>(x8, wn, wd4, out8,
                                      n8, d8 - 1, shift);
}